// round 17
// baseline (speedup 1.0000x reference)
#include <cuda_runtime.h>

// AREMA: attack/release envelope follower.
// y_t = alpha*x_t + (1-alpha)*y_{t-1}, alpha = a if (x_t - y_{t-1} > 0) else r.
// Since a > r > 0:  y_t = max( fma(a, x-y, y), fma(r, x-y, y) ).
//
// R17: interaction probe UNR=32 bursts x __stwt write-through stores.
//  - UNR=32 alone: best kernel (85.9us, 6.2 TB/s) but +10us wall penalty,
//    hypothesized to be dirty-L2 writeback churn in steady-state replay.
//  - __stwt alone: best UNR=16 kernel (87.2us, 6.17 TB/s), wall neutral.
//  - Write-through leaves NO dirty L2 lines -> if the hypothesis is right,
//    this combo keeps the burst win at the wall (~90-91us); if DVFS-driven,
//    wall ~96+ and the R9 __stcs champion stands.
// Config otherwise frozen: CHUNKS=32, WARM=96 (err 6.12e-4, measured x8),
// float2 lanes, 512 blocks x 128 threads, traffic at the 536 MB floor.

#define BB 8
#define TT 16384
#define FF2 256             // feature columns in float2 units (512 floats)
#define CHUNKS 32
#define LCH (TT / CHUNKS)   // 512 outputs per chunk -> 16 phases of UNR=32
#define WARM 96             // 3 warm phases of 32
#define UNR 32

#define LOAD(buf)                                                   \
    _Pragma("unroll")                                               \
    for (int u = 0; u < UNR; ++u) buf[u] = xp[u * FF2];             \
    xp += UNR * FF2;

#define STEP(v)                                                     \
    {                                                               \
        float d0 = (v).x - y0;                                      \
        float d1 = (v).y - y1;                                      \
        y0 = fmaxf(fmaf(A, d0, y0), fmaf(R, d0, y0));               \
        y1 = fmaxf(fmaf(A, d1, y1), fmaf(R, d1, y1));               \
    }

#define COMP(buf)                                                   \
    _Pragma("unroll")                                               \
    for (int u = 0; u < UNR; ++u) STEP(buf[u])

#define COMPST(buf)                                                 \
    _Pragma("unroll")                                               \
    for (int u = 0; u < UNR; ++u) {                                 \
        STEP(buf[u])                                                \
        float2 o; o.x = y0; o.y = y1;                               \
        __stwt(yp + u * FF2, o);                                    \
    }                                                               \
    yp += UNR * FF2;

__global__ __launch_bounds__(128)
void arema_kernel(const float2* __restrict__ x, float2* __restrict__ y) {
    const float A = 0.18126924692201818f;   // 1 - exp(-0.001/0.005)
    const float R = 0.019801326693244747f;  // 1 - exp(-0.001/0.05)

    const int f2 = blockIdx.x * 128 + threadIdx.x;  // float2 lane (coalesced)
    const int b  = blockIdx.y;                      // batch
    const int c  = blockIdx.z;                      // chunk along T

    const int t0 = c * LCH;

    float2 bufA[UNR], bufB[UNR];
    float y0 = 0.0f, y1 = 0.0f;

    const float2* xp;
    float2*       yp = y + (b * TT + t0) * FF2 + f2;

    if (c != 0) {
        // warm-up: 3 phases of 32 (96 steps), read-only.
        // Ends with bufB holding the first MAIN batch (m0).
        xp = x + (b * TT + t0 - WARM) * FF2 + f2;
        LOAD(bufA)                 // w0
        LOAD(bufB)  COMP(bufA)     // w1 in flight, consume w0
        LOAD(bufA)  COMP(bufB)     // w2 in flight, consume w1
        LOAD(bufB)  COMP(bufA)     // m0 in flight, consume w2
    } else {
        // chunk 0: exact, no warm-up; prologue loads m0 into bufB.
        xp = x + (b * TT) * FF2 + f2;
        LOAD(bufB)
    }

    // ---- unified main: 16 phases (m0..m15), bufB = m0 on entry ----
    #pragma unroll 1
    for (int i = 0; i < 7; ++i) {
        LOAD(bufA)                 // m(2i+1)
        COMPST(bufB)               // m(2i)
        LOAD(bufB)                 // m(2i+2)
        COMPST(bufA)               // m(2i+1)
    }
    LOAD(bufA)                     // m15
    COMPST(bufB)                   // m14
    COMPST(bufA)                   // m15
}

extern "C" void kernel_launch(void* const* d_in, const int* in_sizes, int n_in,
                              void* d_out, int out_size) {
    const float2* x = (const float2*)d_in[0];
    float2*       y = (float2*)d_out;
    dim3 grid(FF2 / 128, BB, CHUNKS);  // (2, 8, 32) = 512 blocks x 128 threads
    arema_kernel<<<grid, 128>>>(x, y);
}